// round 4
// baseline (speedup 1.0000x reference)
#include <cuda_runtime.h>
#include <cstdint>
#include <cstddef>

#define B_SZ 1024
#define NF   800
#define L1D  1024

// Scratch (no allocation allowed — __device__ globals)
__device__ float g_vals[B_SZ * NF];   // gated conv features (tf32-rounded), (B,800)
__device__ float g_bw[NF * L1D];      // ft_w tf32-rounded
__device__ float g_l0[B_SZ * L1D];    // clipped features, (B,1024)

__device__ __forceinline__ float tf32r(float v) {
    uint32_t u;
    asm("cvt.rna.tf32.f32 %0, %1;" : "=r"(u) : "f"(v));
    return __uint_as_float(u);
}

// ---------------------------------------------------------------------------
// Kernel 0: round ft_w to tf32 (unbiased RNA) once per launch.
// ---------------------------------------------------------------------------
__global__ __launch_bounds__(256) void prep_bw_kernel(const float* __restrict__ w) {
    int i = blockIdx.x * 256 + threadIdx.x;   // float4 index; grid covers exactly
    float4 v = ((const float4*)w)[i];
    float4 o;
    o.x = tf32r(v.x); o.y = tf32r(v.y); o.z = tf32r(v.z); o.w = tf32r(v.w);
    ((float4*)g_bw)[i] = o;
}

// ---------------------------------------------------------------------------
// Kernel 1: conv(3x3, stride10, pad1) + clip + sigmoid gate, smem-staged rows.
// Block per batch image; stage the 29 needed rows coalesced, compute 100 pos.
// ---------------------------------------------------------------------------
__global__ __launch_bounds__(128) void conv_act_kernel(
    const float* __restrict__ images, const float* __restrict__ conv_w) {
    __shared__ float w[216];
    __shared__ float s[30][3][98];   // s[3k+j][c][x+1] = img[c][10k-1+j][x]; row0/col0 = pad zeros
    int t = threadIdx.x;
    for (int i = t; i < 216; i += 128) w[i] = conv_w[i];
    float* sf = &s[0][0][0];
    for (int i = t; i < 30 * 3 * 98; i += 128) sf[i] = 0.f;
    __syncthreads();

    int b = blockIdx.x;
    const float* img = images + (size_t)b * 3 * 96 * 96;
    for (int i = t; i < 30 * 3 * 96; i += 128) {
        int rr = i / 288; int rem = i - rr * 288;
        int c = rem / 96;  int x = rem - c * 96;
        if (rr) {   // rr==0 is the iy=-1 pad row, stays zero
            int iy = (rr / 3) * 10 - 1 + rr % 3;
            s[rr][c][x + 1] = __ldg(img + c * 9216 + iy * 96 + x);
        }
    }
    __syncthreads();

    if (t < 100) {
        int oy = t / 10, ox = t - oy * 10;
        float acc[8];
#pragma unroll
        for (int c8 = 0; c8 < 8; c8++) acc[c8] = 0.f;
#pragma unroll
        for (int ky = 0; ky < 3; ky++) {
            const float (*srow)[98] = s[3 * oy + ky];
#pragma unroll
            for (int ic = 0; ic < 3; ic++) {
#pragma unroll
                for (int kx = 0; kx < 3; kx++) {
                    float v = srow[ic][10 * ox + kx];
#pragma unroll
                    for (int c8 = 0; c8 < 8; c8++)
                        acc[c8] = fmaf(v, w[c8 * 27 + ic * 9 + ky * 3 + kx], acc[c8]);
                }
            }
        }
#pragma unroll
        for (int c8 = 0; c8 < 8; c8++) {
            float x  = fminf(fmaxf(acc[c8], -1.f), 1.f);
            float sg = 1.f / (1.f + __expf(-10.f * x));
            float vv = (sg > 0.5f) ? sg : 0.f;
            g_vals[(size_t)b * NF + c8 * 100 + t] = tf32r(vv);
        }
    }
}

// ---------------------------------------------------------------------------
// Kernel 2: features = vals(1024x800) @ g_bw(800x1024) + bias, clip [0,1].
// tf32 mma.sync m16n8k8. BM=64 BN=128 BK=16, 256 thr, 8 warps (2x4), warp 32x32.
// 2-stage cp.async double buffer. Smem strides 20/136 -> conflict-free frag LDS.
// ---------------------------------------------------------------------------
__device__ __forceinline__ void mma_tf32(float* d, const uint32_t* a, const uint32_t* b) {
    asm volatile(
        "mma.sync.aligned.m16n8k8.row.col.f32.tf32.tf32.f32 "
        "{%0,%1,%2,%3}, {%4,%5,%6,%7}, {%8,%9}, {%0,%1,%2,%3};\n"
        : "+f"(d[0]), "+f"(d[1]), "+f"(d[2]), "+f"(d[3])
        : "r"(a[0]), "r"(a[1]), "r"(a[2]), "r"(a[3]), "r"(b[0]), "r"(b[1]));
}

#define CP16(dst, src) \
    asm volatile("cp.async.ca.shared.global [%0], [%1], 16;\n" :: "r"(dst), "l"(src))

__global__ __launch_bounds__(256) void feat_mma_kernel(const float* __restrict__ bias) {
    __shared__ float As[2][64][20];    // [stage][m][k], stride 20
    __shared__ float Bs[2][16][136];   // [stage][k][n], stride 136

    const int t = threadIdx.x, lane = t & 31, wid = t >> 5;
    const int wm = wid >> 2, wn = wid & 3;           // 2 x 4 warps
    const int bm = blockIdx.y * 64, bn = blockIdx.x * 128;

    float acc[2][4][4];
#pragma unroll
    for (int f = 0; f < 2; f++)
#pragma unroll
        for (int j = 0; j < 4; j++)
#pragma unroll
            for (int e = 0; e < 4; e++) acc[f][j][e] = 0.f;

    // staging assignments (16B chunks)
    const int a_row = t >> 2, a_seg = (t & 3) << 2;           // 256 chunks = 64x16 A tile
    const int b_row = t >> 5, b_seg = (t & 31) << 2;          // +2nd chunk at b_row+8
    const float* a_src  = g_vals + (size_t)(bm + a_row) * NF + a_seg;
    const float* b_src0 = g_bw + (size_t)b_row * L1D + bn + b_seg;
    const float* b_src1 = g_bw + (size_t)(b_row + 8) * L1D + bn + b_seg;
    uint32_t a_dst[2], b_dst0[2], b_dst1[2];
#pragma unroll
    for (int s2 = 0; s2 < 2; s2++) {
        a_dst[s2]  = (uint32_t)__cvta_generic_to_shared(&As[s2][a_row][a_seg]);
        b_dst0[s2] = (uint32_t)__cvta_generic_to_shared(&Bs[s2][b_row][b_seg]);
        b_dst1[s2] = (uint32_t)__cvta_generic_to_shared(&Bs[s2][b_row + 8][b_seg]);
    }

#define LOAD_STAGE(s2, k0)                                   \
    do {                                                     \
        CP16(a_dst[s2], a_src + (k0));                       \
        CP16(b_dst0[s2], b_src0 + (size_t)(k0) * L1D);       \
        CP16(b_dst1[s2], b_src1 + (size_t)(k0) * L1D);       \
        asm volatile("cp.async.commit_group;\n");            \
    } while (0)

    LOAD_STAGE(0, 0);

    for (int it = 0; it < 50; it++) {
        int buf = it & 1;
        if (it < 49) {
            LOAD_STAGE(buf ^ 1, (it + 1) * 16);
            asm volatile("cp.async.wait_group 1;\n");
        } else {
            asm volatile("cp.async.wait_group 0;\n");
        }
        __syncthreads();

#pragma unroll
        for (int ks = 0; ks < 2; ks++) {
            uint32_t af[2][4];
            int r0 = wm * 32 + (lane >> 2);
            int c0 = ks * 8 + (lane & 3);
#pragma unroll
            for (int f = 0; f < 2; f++) {
                int r = r0 + f * 16;
                af[f][0] = __float_as_uint(As[buf][r][c0]);
                af[f][1] = __float_as_uint(As[buf][r + 8][c0]);
                af[f][2] = __float_as_uint(As[buf][r][c0 + 4]);
                af[f][3] = __float_as_uint(As[buf][r + 8][c0 + 4]);
            }
            uint32_t bf[4][2];
            int kk  = ks * 8 + (lane & 3);
            int nn0 = wn * 32 + (lane >> 2);
#pragma unroll
            for (int j = 0; j < 4; j++) {
                bf[j][0] = __float_as_uint(Bs[buf][kk][nn0 + j * 8]);
                bf[j][1] = __float_as_uint(Bs[buf][kk + 4][nn0 + j * 8]);
            }
#pragma unroll
            for (int f = 0; f < 2; f++)
#pragma unroll
                for (int j = 0; j < 4; j++)
                    mma_tf32(acc[f][j], af[f], bf[j]);
        }
        __syncthreads();
    }

    // epilogue: bias + clip[0,1] -> g_l0
    int q = lane & 3, g = lane >> 2;
#pragma unroll
    for (int f = 0; f < 2; f++) {
        int row0 = bm + wm * 32 + f * 16 + g;
#pragma unroll
        for (int j = 0; j < 4; j++) {
            int col = bn + wn * 32 + j * 8 + 2 * q;
            float bv0 = __ldg(bias + col), bv1 = __ldg(bias + col + 1);
            float2 o0, o1;
            o0.x = fminf(fmaxf(acc[f][j][0] + bv0, 0.f), 1.f);
            o0.y = fminf(fmaxf(acc[f][j][1] + bv1, 0.f), 1.f);
            o1.x = fminf(fmaxf(acc[f][j][2] + bv0, 0.f), 1.f);
            o1.y = fminf(fmaxf(acc[f][j][3] + bv1, 0.f), 1.f);
            *(float2*)(g_l0 + (size_t)row0 * L1D + col) = o0;
            *(float2*)(g_l0 + (size_t)(row0 + 8) * L1D + col) = o1;
        }
    }
}

// ---------------------------------------------------------------------------
// Kernel 3: tail MLP, one warp per sample (unchanged from R3).
// ---------------------------------------------------------------------------
__global__ __launch_bounds__(256) void tail_kernel(
    const float* __restrict__ w1, const float* __restrict__ b1,
    const float* __restrict__ w2, const float* __restrict__ b2,
    const float* __restrict__ w3, const float* __restrict__ b3,
    float* __restrict__ out) {
    int warp = (blockIdx.x * 256 + threadIdx.x) >> 5;
    int lane = threadIdx.x & 31;
    if (warp >= B_SZ) return;

    const float* x = g_l0 + (size_t)warp * L1D + lane * 32;
    const float KC = 127.f / 128.f;

    float c4[8][4];
#pragma unroll
    for (int g = 0; g < 8; g++) {
        float4 r = *(const float4*)(x + g * 4);
        float rr[4] = {r.x, r.y, r.z, r.w};
#pragma unroll
        for (int e = 0; e < 4; e++) {
            float other = __shfl_xor_sync(0xffffffffu, rr[e], 16);
            c4[g][e] = (lane < 16) ? (rr[e] * other * KC) : (other * KC);
        }
    }

    float h1[15];
#pragma unroll
    for (int o = 0; o < 15; o++) {
        const float* wr = w1 + (size_t)o * L1D + lane * 32;
        float a = 0.f;
#pragma unroll
        for (int g = 0; g < 8; g++) {
            float4 wv = *(const float4*)(wr + g * 4);
            a = fmaf(c4[g][0], wv.x, a);
            a = fmaf(c4[g][1], wv.y, a);
            a = fmaf(c4[g][2], wv.z, a);
            a = fmaf(c4[g][3], wv.w, a);
        }
#pragma unroll
        for (int s = 16; s; s >>= 1) a += __shfl_xor_sync(0xffffffffu, a, s);
        h1[o] = fmaxf(a + __ldg(b1 + o), 0.f);
    }

    float h2 = __ldg(b2 + lane);
#pragma unroll
    for (int k = 0; k < 15; k++)
        h2 = fmaf(h1[k], __ldg(w2 + lane * 15 + k), h2);
    h2 = fmaxf(h2, 0.f);

    float ov = h2 * __ldg(w3 + lane);
#pragma unroll
    for (int s = 16; s; s >>= 1) ov += __shfl_xor_sync(0xffffffffu, ov, s);
    if (lane == 0) out[warp] = ov + __ldg(b3);
}

// ---------------------------------------------------------------------------
extern "C" void kernel_launch(void* const* d_in, const int* in_sizes, int n_in,
                              void* d_out, int out_size) {
    const float *images = 0, *conv_w = 0, *ft_w = 0, *ft_b = 0;
    const float *w1 = 0, *b1 = 0, *w2 = 0, *b2 = 0, *w3 = 0, *b3 = 0;

    for (int i = 0; i < n_in; i++) {
        const float* p = (const float*)d_in[i];
        switch (in_sizes[i]) {
            case 28311552: images = p; break;
            case 216:      conv_w = p; break;
            case 819200:   ft_w   = p; break;
            case 1024:     ft_b   = p; break;
            case 15360:    w1     = p; break;
            case 15:       b1     = p; break;
            case 480:      w2     = p; break;
            case 32:       if (!b2) b2 = p; else w3 = p; break;
            case 1:        b3     = p; break;
            default: break;
        }
    }
    float* out = (float*)d_out;

    prep_bw_kernel<<<NF * L1D / 4 / 256, 256>>>(ft_w);          // 800 blocks
    conv_act_kernel<<<B_SZ, 128>>>(images, conv_w);

    dim3 g2(L1D / 128, B_SZ / 64);   // 8 x 16 = 128 CTAs
    feat_mma_kernel<<<g2, 256>>>(ft_b);

    tail_kernel<<<B_SZ / 8, 256>>>(w1, b1, w2, b2, w3, b3, out);
}

// round 5
// speedup vs baseline: 1.1802x; 1.1802x over previous
#include <cuda_runtime.h>
#include <cuda_fp16.h>
#include <cstdint>
#include <cstddef>

#define B_SZ 1024
#define NF   800
#define L1D  1024

// Scratch (no allocation allowed — __device__ globals)
__device__ __half g_ah[B_SZ * NF];    // vals hi, (B,800) row-major
__device__ __half g_al[B_SZ * NF];    // vals lo
__device__ __half g_bth[L1D * NF];    // ft_w^T hi, (n, k) n-major
__device__ __half g_btl[L1D * NF];    // ft_w^T lo
__device__ float  g_l0[B_SZ * L1D];   // clipped features, (B,1024)

// ---------------------------------------------------------------------------
// Kernel 0: transpose ft_w (800x1024 -> 1024x800) and split into fp16 hi/lo.
// ---------------------------------------------------------------------------
__global__ __launch_bounds__(256) void prep_bt_kernel(const float* __restrict__ w) {
    __shared__ float ts[32][33];
    int tx = threadIdx.x & 31, ty = threadIdx.x >> 5;   // 32 x 8
    int kbase = blockIdx.y * 32, nbase = blockIdx.x * 32;
#pragma unroll
    for (int i = 0; i < 4; i++)
        ts[ty + i * 8][tx] = w[(size_t)(kbase + ty + i * 8) * L1D + nbase + tx];
    __syncthreads();
#pragma unroll
    for (int i = 0; i < 4; i++) {
        int n = nbase + ty + i * 8;
        int k = kbase + tx;
        float v = ts[tx][ty + i * 8];
        __half h = __float2half_rn(v);
        g_bth[(size_t)n * NF + k] = h;
        g_btl[(size_t)n * NF + k] = __float2half_rn(v - __half2float(h));
    }
}

// ---------------------------------------------------------------------------
// Kernel 1: conv(3x3,s10,p1) + clip + sigmoid gate -> fp16 hi/lo vals.
// Block per image; stage 29 needed rows in smem (pad cells zeroed explicitly).
// ---------------------------------------------------------------------------
__global__ __launch_bounds__(128) void conv_act_kernel(
    const float* __restrict__ images, const float* __restrict__ conv_w) {
    __shared__ float w[216];
    __shared__ float s[30][3][98];   // s[3k+j][c][x+1] = img[c][10k-1+j][x]
    int t = threadIdx.x;
    for (int i = t; i < 216; i += 128) w[i] = conv_w[i];
    // zero pad row (rr=0) and pad column (x index 0) only
    for (int i = t; i < 3 * 98; i += 128) s[0][i / 98][i % 98] = 0.f;
    for (int i = t; i < 30 * 3; i += 128) s[i / 3][i % 3][0] = 0.f;
    __syncthreads();

    int b = blockIdx.x;
    const float* img = images + (size_t)b * 3 * 96 * 96;
    for (int i = t; i < 29 * 3 * 96; i += 128) {   // rr = 1..29
        int rr = i / 288 + 1; int rem = i - (rr - 1) * 288;
        int c = rem / 96;  int x = rem - c * 96;
        int iy = (rr / 3) * 10 - 1 + rr % 3;
        s[rr][c][x + 1] = __ldg(img + c * 9216 + iy * 96 + x);
    }
    __syncthreads();

    if (t < 100) {
        int oy = t / 10, ox = t - oy * 10;
        float acc[8];
#pragma unroll
        for (int c8 = 0; c8 < 8; c8++) acc[c8] = 0.f;
#pragma unroll
        for (int ky = 0; ky < 3; ky++) {
            const float (*srow)[98] = s[3 * oy + ky];
#pragma unroll
            for (int ic = 0; ic < 3; ic++) {
#pragma unroll
                for (int kx = 0; kx < 3; kx++) {
                    float v = srow[ic][10 * ox + kx];
#pragma unroll
                    for (int c8 = 0; c8 < 8; c8++)
                        acc[c8] = fmaf(v, w[c8 * 27 + ic * 9 + ky * 3 + kx], acc[c8]);
                }
            }
        }
#pragma unroll
        for (int c8 = 0; c8 < 8; c8++) {
            float x  = fminf(fmaxf(acc[c8], -1.f), 1.f);
            float sg = 1.f / (1.f + __expf(-10.f * x));
            float vv = (sg > 0.5f) ? sg : 0.f;
            size_t idx = (size_t)b * NF + c8 * 100 + t;
            __half h = __float2half_rn(vv);
            g_ah[idx] = h;
            g_al[idx] = __float2half_rn(vv - __half2float(h));
        }
    }
}

// ---------------------------------------------------------------------------
// Kernel 2: features = vals @ ft_w + bias, clip [0,1]; fp16 hi/lo split mma.
// D = Ah*Bh + Ah*Bl + Al*Bh (fp32 accum). BM=64 BN=128 BK=16, 256 thr,
// 8 warps (2x4), warp 32x32, m16n8k16, 2-stage cp.async.
// Smem u32 stride 12 -> all fragment LDS bank-conflict-free.
// ---------------------------------------------------------------------------
__device__ __forceinline__ void mma_f16(float* d, const uint32_t* a, const uint32_t* b) {
    asm volatile(
        "mma.sync.aligned.m16n8k16.row.col.f32.f16.f16.f32 "
        "{%0,%1,%2,%3}, {%4,%5,%6,%7}, {%8,%9}, {%0,%1,%2,%3};\n"
        : "+f"(d[0]), "+f"(d[1]), "+f"(d[2]), "+f"(d[3])
        : "r"(a[0]), "r"(a[1]), "r"(a[2]), "r"(a[3]), "r"(b[0]), "r"(b[1]));
}

#define CP16(dst, src) \
    asm volatile("cp.async.ca.shared.global [%0], [%1], 16;\n" :: "r"(dst), "l"(src))

__global__ __launch_bounds__(256) void feat_mma_kernel(const float* __restrict__ bias) {
    __shared__ uint32_t Ash[2][64][12];
    __shared__ uint32_t Asl[2][64][12];
    __shared__ uint32_t Bsh[2][128][12];
    __shared__ uint32_t Bsl[2][128][12];

    const int t = threadIdx.x, lane = t & 31, wid = t >> 5;
    const int wm = wid >> 2, wn = wid & 3;           // 2 x 4 warps
    const int bm = blockIdx.y * 64, bn = blockIdx.x * 128;

    float acc[2][4][4];
#pragma unroll
    for (int f = 0; f < 2; f++)
#pragma unroll
        for (int j = 0; j < 4; j++)
#pragma unroll
            for (int e = 0; e < 4; e++) acc[f][j][e] = 0.f;

    // ---- staging assignments: 3 x 16B chunks per thread per stage ----
    // A: 256 chunks (threads 0-127: Ah, 128-255: Al), row = (t&127)>>1, seg = t&1
    const int a_arr = t >> 7, a_row = (t & 127) >> 1, a_seg = t & 1;
    const __half* a_src = (a_arr ? g_al : g_ah) + (size_t)(bm + a_row) * NF + a_seg * 8;
    // B: each thread does one Bh chunk and one Bl chunk: row = t>>1, seg = t&1
    const int b_row = t >> 1, b_seg = t & 1;
    const __half* bh_src = g_bth + (size_t)(bn + b_row) * NF + b_seg * 8;
    const __half* bl_src = g_btl + (size_t)(bn + b_row) * NF + b_seg * 8;
    uint32_t a_dst[2], bh_dst[2], bl_dst[2];
#pragma unroll
    for (int s2 = 0; s2 < 2; s2++) {
        a_dst[s2]  = (uint32_t)__cvta_generic_to_shared(
            a_arr ? &Asl[s2][a_row][a_seg * 4] : &Ash[s2][a_row][a_seg * 4]);
        bh_dst[s2] = (uint32_t)__cvta_generic_to_shared(&Bsh[s2][b_row][b_seg * 4]);
        bl_dst[s2] = (uint32_t)__cvta_generic_to_shared(&Bsl[s2][b_row][b_seg * 4]);
    }

#define LOAD_STAGE(s2, k0)                                   \
    do {                                                     \
        CP16(a_dst[s2],  a_src  + (k0));                     \
        CP16(bh_dst[s2], bh_src + (k0));                     \
        CP16(bl_dst[s2], bl_src + (k0));                     \
        asm volatile("cp.async.commit_group;\n");            \
    } while (0)

    LOAD_STAGE(0, 0);

    const int r0 = wm * 32 + (lane >> 2);
    const int nb = wn * 32 + (lane >> 2);
    const int j0 = lane & 3;

    for (int it = 0; it < 50; it++) {
        int buf = it & 1;
        if (it < 49) {
            LOAD_STAGE(buf ^ 1, (it + 1) * 16);
            asm volatile("cp.async.wait_group 1;\n");
        } else {
            asm volatile("cp.async.wait_group 0;\n");
        }
        __syncthreads();

        uint32_t ah[2][4], al[2][4];
#pragma unroll
        for (int f = 0; f < 2; f++) {
            int r = r0 + f * 16;
            ah[f][0] = Ash[buf][r][j0];      ah[f][1] = Ash[buf][r + 8][j0];
            ah[f][2] = Ash[buf][r][j0 + 4];  ah[f][3] = Ash[buf][r + 8][j0 + 4];
            al[f][0] = Asl[buf][r][j0];      al[f][1] = Asl[buf][r + 8][j0];
            al[f][2] = Asl[buf][r][j0 + 4];  al[f][3] = Asl[buf][r + 8][j0 + 4];
        }
        uint32_t bh[4][2], bl[4][2];
#pragma unroll
        for (int j = 0; j < 4; j++) {
            bh[j][0] = Bsh[buf][nb + j * 8][j0]; bh[j][1] = Bsh[buf][nb + j * 8][j0 + 4];
            bl[j][0] = Bsl[buf][nb + j * 8][j0]; bl[j][1] = Bsl[buf][nb + j * 8][j0 + 4];
        }
#pragma unroll
        for (int f = 0; f < 2; f++)
#pragma unroll
            for (int j = 0; j < 4; j++) {
                mma_f16(acc[f][j], ah[f], bh[j]);
                mma_f16(acc[f][j], ah[f], bl[j]);
                mma_f16(acc[f][j], al[f], bh[j]);
            }
        __syncthreads();
    }

    // epilogue: bias + clip[0,1] -> g_l0
    int q = lane & 3, g = lane >> 2;
#pragma unroll
    for (int f = 0; f < 2; f++) {
        int row0 = bm + wm * 32 + f * 16 + g;
#pragma unroll
        for (int j = 0; j < 4; j++) {
            int col = bn + wn * 32 + j * 8 + 2 * q;
            float bv0 = __ldg(bias + col), bv1 = __ldg(bias + col + 1);
            float2 o0, o1;
            o0.x = fminf(fmaxf(acc[f][j][0] + bv0, 0.f), 1.f);
            o0.y = fminf(fmaxf(acc[f][j][1] + bv1, 0.f), 1.f);
            o1.x = fminf(fmaxf(acc[f][j][2] + bv0, 0.f), 1.f);
            o1.y = fminf(fmaxf(acc[f][j][3] + bv1, 0.f), 1.f);
            *(float2*)(g_l0 + (size_t)row0 * L1D + col) = o0;
            *(float2*)(g_l0 + (size_t)(row0 + 8) * L1D + col) = o1;
        }
    }
}

// ---------------------------------------------------------------------------
// Kernel 3: tail MLP, warp per sample, INTERLEAVED lane ownership:
// lane L owns j = e*32 + L (e = 0..31). Pairing j<->j+512 is lane-local
// (e <-> e+16): no shfl, and all x/w1 loads are fully coalesced.
// ---------------------------------------------------------------------------
__global__ __launch_bounds__(256) void tail_kernel(
    const float* __restrict__ w1, const float* __restrict__ b1,
    const float* __restrict__ w2, const float* __restrict__ b2,
    const float* __restrict__ w3, const float* __restrict__ b3,
    float* __restrict__ out) {
    int warp = (blockIdx.x * 256 + threadIdx.x) >> 5;
    int lane = threadIdx.x & 31;
    if (warp >= B_SZ) return;

    const float* x = g_l0 + (size_t)warp * L1D + lane;
    const float KC = 127.f / 128.f;

    float xv[32];
#pragma unroll
    for (int e = 0; e < 32; e++) xv[e] = x[e * 32];   // coalesced

    float c[32];
#pragma unroll
    for (int e = 0; e < 16; e++) {
        c[e]      = xv[e] * xv[e + 16] * KC;   // l0c[j<512]  = s0*s1*K
        c[e + 16] = xv[e] * KC;                // l0c[j>=512] = s0*K
    }

    float a[15];
#pragma unroll
    for (int o = 0; o < 15; o++) a[o] = 0.f;
    const float* w1p = w1 + lane;
#pragma unroll
    for (int e = 0; e < 32; e++) {
#pragma unroll
        for (int o = 0; o < 15; o++)
            a[o] = fmaf(c[e], __ldg(w1p + (size_t)o * L1D + e * 32), a[o]);
    }
    // one parallel butterfly over all 15 accumulators
#pragma unroll
    for (int s = 16; s; s >>= 1)
#pragma unroll
        for (int o = 0; o < 15; o++)
            a[o] += __shfl_xor_sync(0xffffffffu, a[o], s);

    float h1[15];
#pragma unroll
    for (int o = 0; o < 15; o++) h1[o] = fmaxf(a[o] + __ldg(b1 + o), 0.f);

    float h2 = __ldg(b2 + lane);
#pragma unroll
    for (int k = 0; k < 15; k++)
        h2 = fmaf(h1[k], __ldg(w2 + lane * 15 + k), h2);
    h2 = fmaxf(h2, 0.f);

    float ov = h2 * __ldg(w3 + lane);
#pragma unroll
    for (int s = 16; s; s >>= 1) ov += __shfl_xor_sync(0xffffffffu, ov, s);
    if (lane == 0) out[warp] = ov + __ldg(b3);
}

// ---------------------------------------------------------------------------
extern "C" void kernel_launch(void* const* d_in, const int* in_sizes, int n_in,
                              void* d_out, int out_size) {
    const float *images = 0, *conv_w = 0, *ft_w = 0, *ft_b = 0;
    const float *w1 = 0, *b1 = 0, *w2 = 0, *b2 = 0, *w3 = 0, *b3 = 0;

    for (int i = 0; i < n_in; i++) {
        const float* p = (const float*)d_in[i];
        switch (in_sizes[i]) {
            case 28311552: images = p; break;
            case 216:      conv_w = p; break;
            case 819200:   ft_w   = p; break;
            case 1024:     ft_b   = p; break;
            case 15360:    w1     = p; break;
            case 15:       b1     = p; break;
            case 480:      w2     = p; break;
            case 32:       if (!b2) b2 = p; else w3 = p; break;
            case 1:        b3     = p; break;
            default: break;
        }
    }
    float* out = (float*)d_out;

    dim3 gt(L1D / 32, NF / 32);      // 32 x 25
    prep_bt_kernel<<<gt, 256>>>(ft_w);
    conv_act_kernel<<<B_SZ, 128>>>(images, conv_w);

    dim3 g2(L1D / 128, B_SZ / 64);   // 8 x 16 = 128 CTAs
    feat_mma_kernel<<<g2, 256>>>(ft_b);

    tail_kernel<<<B_SZ / 8, 256>>>(w1, b1, w2, b2, w3, b3, out);
}

// round 7
// speedup vs baseline: 1.4197x; 1.2029x over previous
#include <cuda_runtime.h>
#include <cuda_fp16.h>
#include <cstdint>
#include <cstddef>

#define B_SZ 1024
#define NF   800
#define L1D  1024

// Scratch (no allocation allowed — __device__ globals)
__device__ __half g_a[B_SZ * NF];     // vals fp16 (RN), (B,800) row-major
__device__ __half g_bh[L1D * NF];     // ft_w^T hi, (n,k) k-contig
__device__ __half g_bl[L1D * NF];     // ft_w^T lo
__device__ float  g_l0[B_SZ * L1D];   // clipped features, (B,1024)

// ---------------------------------------------------------------------------
// Kernel 0: transpose ft_w (800x1024 -> 1024x800) and split into fp16 hi/lo.
// ---------------------------------------------------------------------------
__global__ __launch_bounds__(256) void prep_bt_kernel(const float* __restrict__ w) {
    __shared__ float ts[32][33];
    int tx = threadIdx.x & 31, ty = threadIdx.x >> 5;   // 32 x 8
    int kbase = blockIdx.y * 32, nbase = blockIdx.x * 32;
#pragma unroll
    for (int i = 0; i < 4; i++)
        ts[ty + i * 8][tx] = w[(size_t)(kbase + ty + i * 8) * L1D + nbase + tx];
    __syncthreads();
#pragma unroll
    for (int i = 0; i < 4; i++) {
        int n = nbase + ty + i * 8;
        int k = kbase + tx;
        float v = ts[tx][ty + i * 8];
        __half h = __float2half_rn(v);
        g_bh[(size_t)n * NF + k] = h;
        g_bl[(size_t)n * NF + k] = __float2half_rn(v - __half2float(h));
    }
}

// ---------------------------------------------------------------------------
// Kernel 1: conv(3x3,s10,p1) + clip + sigmoid gate -> fp16 vals.
// ---------------------------------------------------------------------------
__global__ __launch_bounds__(128) void conv_act_kernel(
    const float* __restrict__ images, const float* __restrict__ conv_w) {
    __shared__ float w[216];
    __shared__ float s[30][3][98];
    int t = threadIdx.x;
    int b = blockIdx.x;
    for (int i = t; i < 216; i += 128) w[i] = conv_w[i];
    for (int i = t; i < 3 * 98; i += 128) s[0][i / 98][i % 98] = 0.f;
    for (int i = t; i < 30 * 3; i += 128) s[i / 3][i % 3][0] = 0.f;
    __syncthreads();

    const float* img = images + (size_t)b * 3 * 96 * 96;
    for (int i = t; i < 29 * 3 * 96; i += 128) {
        int rr = i / 288 + 1; int rem = i - (rr - 1) * 288;
        int c = rem / 96;  int x = rem - c * 96;
        int iy = (rr / 3) * 10 - 1 + rr % 3;
        s[rr][c][x + 1] = __ldg(img + c * 9216 + iy * 96 + x);
    }
    __syncthreads();

    if (t < 100) {
        int oy = t / 10, ox = t - oy * 10;
        float acc[8];
#pragma unroll
        for (int c8 = 0; c8 < 8; c8++) acc[c8] = 0.f;
#pragma unroll
        for (int ky = 0; ky < 3; ky++) {
            const float (*srow)[98] = s[3 * oy + ky];
#pragma unroll
            for (int ic = 0; ic < 3; ic++) {
#pragma unroll
                for (int kx = 0; kx < 3; kx++) {
                    float v = srow[ic][10 * ox + kx];
#pragma unroll
                    for (int c8 = 0; c8 < 8; c8++)
                        acc[c8] = fmaf(v, w[c8 * 27 + ic * 9 + ky * 3 + kx], acc[c8]);
                }
            }
        }
#pragma unroll
        for (int c8 = 0; c8 < 8; c8++) {
            float x  = fminf(fmaxf(acc[c8], -1.f), 1.f);
            float sg = 1.f / (1.f + __expf(-10.f * x));
            float vv = (sg > 0.5f) ? sg : 0.f;
            g_a[(size_t)b * NF + c8 * 100 + t] = __float2half_rn(vv);
        }
    }
}

// ---------------------------------------------------------------------------
// Kernel 2: features = vals @ ft_w + bias, clip [0,1].
// D = A*Bh + A*Bl (fp32 accum), m16n8k16. BM=BN=64, BK=16, 128 thr,
// 4 warps (2x2), warp 32x32. 2-stage cp.async. 18KB smem -> high occupancy.
// ---------------------------------------------------------------------------
__device__ __forceinline__ void mma_f16(float* d, const uint32_t* a, const uint32_t* b) {
    asm volatile(
        "mma.sync.aligned.m16n8k16.row.col.f32.f16.f16.f32 "
        "{%0,%1,%2,%3}, {%4,%5,%6,%7}, {%8,%9}, {%0,%1,%2,%3};\n"
        : "+f"(d[0]), "+f"(d[1]), "+f"(d[2]), "+f"(d[3])
        : "r"(a[0]), "r"(a[1]), "r"(a[2]), "r"(a[3]), "r"(b[0]), "r"(b[1]));
}

#define CP16(dst, src) \
    asm volatile("cp.async.ca.shared.global [%0], [%1], 16;\n" :: "r"(dst), "l"(src))

__global__ __launch_bounds__(128) void feat_mma_kernel(const float* __restrict__ bias) {
    __shared__ uint32_t As[2][64][12];
    __shared__ uint32_t Bh[2][64][12];
    __shared__ uint32_t Bl[2][64][12];

    const int t = threadIdx.x, lane = t & 31, wid = t >> 5;
    const int wm = wid >> 1, wn = wid & 1;           // 2 x 2 warps, 32x32 tiles
    const int bm = blockIdx.y * 64, bn = blockIdx.x * 64;

    float acc[2][4][4];
#pragma unroll
    for (int f = 0; f < 2; f++)
#pragma unroll
        for (int j = 0; j < 4; j++)
#pragma unroll
            for (int e = 0; e < 4; e++) acc[f][j][e] = 0.f;

    // staging: 3 x 16B chunks per thread per stage (A, Bh, Bl: 128 chunks each)
    const int row = t >> 1, seg = t & 1;
    const __half* a_src  = g_a  + (size_t)(bm + row) * NF + seg * 8;
    const __half* bh_src = g_bh + (size_t)(bn + row) * NF + seg * 8;
    const __half* bl_src = g_bl + (size_t)(bn + row) * NF + seg * 8;
    uint32_t a_dst[2], bh_dst[2], bl_dst[2];
#pragma unroll
    for (int s2 = 0; s2 < 2; s2++) {
        a_dst[s2]  = (uint32_t)__cvta_generic_to_shared(&As[s2][row][seg * 4]);
        bh_dst[s2] = (uint32_t)__cvta_generic_to_shared(&Bh[s2][row][seg * 4]);
        bl_dst[s2] = (uint32_t)__cvta_generic_to_shared(&Bl[s2][row][seg * 4]);
    }

#define LOAD_STAGE(s2, k0)                                   \
    do {                                                     \
        CP16(a_dst[s2],  a_src  + (k0));                     \
        CP16(bh_dst[s2], bh_src + (k0));                     \
        CP16(bl_dst[s2], bl_src + (k0));                     \
        asm volatile("cp.async.commit_group;\n");            \
    } while (0)

    LOAD_STAGE(0, 0);

    const int r0 = wm * 32 + (lane >> 2);
    const int nb = wn * 32 + (lane >> 2);
    const int j0 = lane & 3;

    for (int it = 0; it < 50; it++) {
        int buf = it & 1;
        if (it < 49) {
            LOAD_STAGE(buf ^ 1, (it + 1) * 16);
            asm volatile("cp.async.wait_group 1;\n");
        } else {
            asm volatile("cp.async.wait_group 0;\n");
        }
        __syncthreads();

        uint32_t af[2][4];
#pragma unroll
        for (int f = 0; f < 2; f++) {
            int r = r0 + f * 16;
            af[f][0] = As[buf][r][j0];      af[f][1] = As[buf][r + 8][j0];
            af[f][2] = As[buf][r][j0 + 4];  af[f][3] = As[buf][r + 8][j0 + 4];
        }
        uint32_t bhf[4][2], blf[4][2];
#pragma unroll
        for (int j = 0; j < 4; j++) {
            bhf[j][0] = Bh[buf][nb + j * 8][j0]; bhf[j][1] = Bh[buf][nb + j * 8][j0 + 4];
            blf[j][0] = Bl[buf][nb + j * 8][j0]; blf[j][1] = Bl[buf][nb + j * 8][j0 + 4];
        }
#pragma unroll
        for (int f = 0; f < 2; f++)
#pragma unroll
            for (int j = 0; j < 4; j++) {
                mma_f16(acc[f][j], af[f], bhf[j]);
                mma_f16(acc[f][j], af[f], blf[j]);
            }
        __syncthreads();
    }

    // epilogue: bias + clip[0,1] -> g_l0
    int q = lane & 3, g = lane >> 2;
#pragma unroll
    for (int f = 0; f < 2; f++) {
        int row0 = bm + wm * 32 + f * 16 + g;
#pragma unroll
        for (int j = 0; j < 4; j++) {
            int col = bn + wn * 32 + j * 8 + 2 * q;
            float bv0 = __ldg(bias + col), bv1 = __ldg(bias + col + 1);
            float2 o0, o1;
            o0.x = fminf(fmaxf(acc[f][j][0] + bv0, 0.f), 1.f);
            o0.y = fminf(fmaxf(acc[f][j][1] + bv1, 0.f), 1.f);
            o1.x = fminf(fmaxf(acc[f][j][2] + bv0, 0.f), 1.f);
            o1.y = fminf(fmaxf(acc[f][j][3] + bv1, 0.f), 1.f);
            *(float2*)(g_l0 + (size_t)row0 * L1D + col) = o0;
            *(float2*)(g_l0 + (size_t)(row0 + 8) * L1D + col) = o1;
        }
    }
}

// ---------------------------------------------------------------------------
// Kernel 3: tail MLP. 4 warps per sample (K-split), 2 samples per 256-thr CTA,
// 512 CTAs -> 4096 warps. Warp q covers l0c indices j in [q*256, q*256+256).
// ---------------------------------------------------------------------------
__global__ __launch_bounds__(256) void tail_kernel(
    const float* __restrict__ w1, const float* __restrict__ b1,
    const float* __restrict__ w2, const float* __restrict__ b2,
    const float* __restrict__ w3, const float* __restrict__ b3,
    float* __restrict__ out) {
    __shared__ float part[2][4][15];
    __shared__ float h1s[2][15];

    const int t = threadIdx.x, lane = t & 31, wid = t >> 5;
    const int sl = wid >> 2, q = wid & 3;          // sample-local, quarter
    const int sample = blockIdx.x * 2 + sl;
    const float* x = g_l0 + (size_t)sample * L1D;
    const float KCst = 127.f / 128.f;

    float c[8];
    if (q < 2) {
#pragma unroll
        for (int i = 0; i < 8; i++) {
            int e = q * 8 + i;
            c[i] = x[e * 32 + lane] * x[(e + 16) * 32 + lane] * KCst;
        }
    } else {
#pragma unroll
        for (int i = 0; i < 8; i++) {
            int e = (q - 2) * 8 + i;
            c[i] = x[e * 32 + lane] * KCst;
        }
    }

    float a[15];
#pragma unroll
    for (int o = 0; o < 15; o++) a[o] = 0.f;
    const int jbase = q * 256 + lane;
#pragma unroll
    for (int i = 0; i < 8; i++) {
#pragma unroll
        for (int o = 0; o < 15; o++)
            a[o] = fmaf(c[i], __ldg(w1 + (size_t)o * L1D + jbase + i * 32), a[o]);
    }
#pragma unroll
    for (int s = 16; s; s >>= 1)
#pragma unroll
        for (int o = 0; o < 15; o++)
            a[o] += __shfl_xor_sync(0xffffffffu, a[o], s);
    if (lane < 15) part[sl][q][lane] = a[lane];
    __syncthreads();

    if (q == 0 && lane < 15) {
        float h = part[sl][0][lane] + part[sl][1][lane]
                + part[sl][2][lane] + part[sl][3][lane] + __ldg(b1 + lane);
        h1s[sl][lane] = fmaxf(h, 0.f);
    }
    __syncthreads();

    if (q == 0) {
        float h2 = __ldg(b2 + lane);
#pragma unroll
        for (int k = 0; k < 15; k++)
            h2 = fmaf(h1s[sl][k], __ldg(w2 + lane * 15 + k), h2);
        h2 = fmaxf(h2, 0.f);
        float ov = h2 * __ldg(w3 + lane);
#pragma unroll
        for (int s = 16; s; s >>= 1) ov += __shfl_xor_sync(0xffffffffu, ov, s);
        if (lane == 0) out[sample] = ov + __ldg(b3);
    }
}

// ---------------------------------------------------------------------------
extern "C" void kernel_launch(void* const* d_in, const int* in_sizes, int n_in,
                              void* d_out, int out_size) {
    const float *images = 0, *conv_w = 0, *ft_w = 0, *ft_b = 0;
    const float *w1 = 0, *b1 = 0, *w2 = 0, *b2 = 0, *w3 = 0, *b3 = 0;

    for (int i = 0; i < n_in; i++) {
        const float* p = (const float*)d_in[i];
        switch (in_sizes[i]) {
            case 28311552: images = p; break;
            case 216:      conv_w = p; break;
            case 819200:   ft_w   = p; break;
            case 1024:     ft_b   = p; break;
            case 15360:    w1     = p; break;
            case 15:       b1     = p; break;
            case 480:      w2     = p; break;
            case 32:       if (!b2) b2 = p; else w3 = p; break;
            case 1:        b3     = p; break;
            default: break;
        }
    }
    float* out = (float*)d_out;

    dim3 gt(L1D / 32, NF / 32);      // 32 x 25
    prep_bt_kernel<<<gt, 256>>>(ft_w);
    conv_act_kernel<<<B_SZ, 128>>>(images, conv_w);

    dim3 g2(L1D / 64, B_SZ / 64);    // 16 x 16 = 256 CTAs
    feat_mma_kernel<<<g2, 128>>>(ft_b);

    tail_kernel<<<B_SZ / 2, 256>>>(w1, b1, w2, b2, w3, b3, out);
}